// round 1
// baseline (speedup 1.0000x reference)
#include <cuda_runtime.h>

// Problem constants
#define BSZ   16
#define MOUT  128
#define CBLK  8
#define NCH   1024
#define TLEN  2048
#define T4    (TLEN / 4)   // 512 float4 per row

// Ax[b,m,t] = sum_c x[b, m*8+c, t] * tanh(blocks[m,c])
// One CTA per (b,m): reads 8 contiguous rows of length T, writes 1 row.
__global__ void __launch_bounds__(256, 8)
ax_kernel(const float* __restrict__ x,
          const float* __restrict__ blocks,
          float* __restrict__ out)
{
    const int bm = blockIdx.x;            // 0 .. BSZ*MOUT-1
    const int m  = bm & (MOUT - 1);
    const int b  = bm >> 7;               // bm / MOUT

    __shared__ float ws[CBLK];
    if (threadIdx.x < CBLK)
        ws[threadIdx.x] = tanhf(blocks[m * CBLK + threadIdx.x]);
    __syncthreads();

    // Copy weights to registers (broadcast LDS, conflict-free)
    float w0 = ws[0], w1 = ws[1], w2 = ws[2], w3 = ws[3];
    float w4 = ws[4], w5 = ws[5], w6 = ws[6], w7 = ws[7];

    const float4* __restrict__ xb =
        reinterpret_cast<const float4*>(x + ((size_t)b * NCH + (size_t)m * CBLK) * TLEN);
    float4* __restrict__ ob =
        reinterpret_cast<float4*>(out + ((size_t)b * MOUT + m) * TLEN);

    #pragma unroll
    for (int it = 0; it < T4 / 256; ++it) {
        const int t = threadIdx.x + it * 256;

        // Front-batch all 8 loads for MLP
        float4 v0 = xb[0 * T4 + t];
        float4 v1 = xb[1 * T4 + t];
        float4 v2 = xb[2 * T4 + t];
        float4 v3 = xb[3 * T4 + t];
        float4 v4 = xb[4 * T4 + t];
        float4 v5 = xb[5 * T4 + t];
        float4 v6 = xb[6 * T4 + t];
        float4 v7 = xb[7 * T4 + t];

        float4 acc;
        acc.x = v0.x * w0; acc.y = v0.y * w0; acc.z = v0.z * w0; acc.w = v0.w * w0;
        acc.x += v1.x * w1; acc.y += v1.y * w1; acc.z += v1.z * w1; acc.w += v1.w * w1;
        acc.x += v2.x * w2; acc.y += v2.y * w2; acc.z += v2.z * w2; acc.w += v2.w * w2;
        acc.x += v3.x * w3; acc.y += v3.y * w3; acc.z += v3.z * w3; acc.w += v3.w * w3;
        acc.x += v4.x * w4; acc.y += v4.y * w4; acc.z += v4.z * w4; acc.w += v4.w * w4;
        acc.x += v5.x * w5; acc.y += v5.y * w5; acc.z += v5.z * w5; acc.w += v5.w * w5;
        acc.x += v6.x * w6; acc.y += v6.y * w6; acc.z += v6.z * w6; acc.w += v6.w * w6;
        acc.x += v7.x * w7; acc.y += v7.y * w7; acc.z += v7.z * w7; acc.w += v7.w * w7;

        ob[t] = acc;
    }
}

// A_full[i, j] = (j>>3 == i) ? tanh(blocks[j]) : 0   for i in [0,128), j in [0,1024)
__global__ void afull_kernel(const float* __restrict__ blocks,
                             float* __restrict__ out)
{
    const int idx = blockIdx.x * blockDim.x + threadIdx.x;  // over MOUT*NCH = 131072
    if (idx < MOUT * NCH) {
        const int i = idx >> 10;       // / 1024
        const int j = idx & 1023;
        out[idx] = ((j >> 3) == i) ? tanhf(blocks[j]) : 0.0f;
    }
}

extern "C" void kernel_launch(void* const* d_in, const int* in_sizes, int n_in,
                              void* d_out, int out_size)
{
    const float* x      = (const float*)d_in[0];
    const float* blocks = (const float*)d_in[1];
    float* out = (float*)d_out;

    // Output layout: Ax (B*M*T floats) followed by A_full (M*NCH floats)
    float* ax_out    = out;
    float* afull_out = out + (size_t)BSZ * MOUT * TLEN;

    ax_kernel<<<BSZ * MOUT, 256>>>(x, blocks, ax_out);
    afull_kernel<<<(MOUT * NCH + 255) / 256, 256>>>(blocks, afull_out);
}

// round 2
// speedup vs baseline: 1.0967x; 1.0967x over previous
#include <cuda_runtime.h>

// Problem constants
#define BSZ   16
#define MOUT  128
#define CBLK  8
#define NCH   1024
#define TLEN  2048
#define T4    (TLEN / 4)   // 512 float4 per row

// Fused kernel:
//  Ax[b,m,t] = sum_c x[b, m*8+c, t] * tanh(blocks[m,c])
//  One CTA per (b,m): reads 8 contiguous rows of length T, writes 1 row.
//  CTAs with b==0 additionally write A_full row m (block-diagonal of tanh).
__global__ void __launch_bounds__(256, 8)
fused_kernel(const float* __restrict__ x,
             const float* __restrict__ blocks,
             float* __restrict__ ax_out,
             float* __restrict__ afull_out)
{
    const int bm = blockIdx.x;            // 0 .. BSZ*MOUT-1
    const int m  = bm & (MOUT - 1);
    const int b  = bm >> 7;               // bm / MOUT

    __shared__ float ws[CBLK];
    if (threadIdx.x < CBLK)
        ws[threadIdx.x] = tanhf(blocks[m * CBLK + threadIdx.x]);
    __syncthreads();

    // Copy weights to registers (broadcast LDS, conflict-free)
    float w0 = ws[0], w1 = ws[1], w2 = ws[2], w3 = ws[3];
    float w4 = ws[4], w5 = ws[5], w6 = ws[6], w7 = ws[7];

    const float4* __restrict__ xb =
        reinterpret_cast<const float4*>(x + ((size_t)b * NCH + (size_t)m * CBLK) * TLEN);
    float4* __restrict__ ob =
        reinterpret_cast<float4*>(ax_out + ((size_t)b * MOUT + m) * TLEN);

    #pragma unroll
    for (int it = 0; it < T4 / 256; ++it) {
        const int t = threadIdx.x + it * 256;

        // Front-batch all 8 loads for MLP
        float4 v0 = xb[0 * T4 + t];
        float4 v1 = xb[1 * T4 + t];
        float4 v2 = xb[2 * T4 + t];
        float4 v3 = xb[3 * T4 + t];
        float4 v4 = xb[4 * T4 + t];
        float4 v5 = xb[5 * T4 + t];
        float4 v6 = xb[6 * T4 + t];
        float4 v7 = xb[7 * T4 + t];

        float4 acc;
        acc.x = v0.x * w0; acc.y = v0.y * w0; acc.z = v0.z * w0; acc.w = v0.w * w0;
        acc.x += v1.x * w1; acc.y += v1.y * w1; acc.z += v1.z * w1; acc.w += v1.w * w1;
        acc.x += v2.x * w2; acc.y += v2.y * w2; acc.z += v2.z * w2; acc.w += v2.w * w2;
        acc.x += v3.x * w3; acc.y += v3.y * w3; acc.z += v3.z * w3; acc.w += v3.w * w3;
        acc.x += v4.x * w4; acc.y += v4.y * w4; acc.z += v4.z * w4; acc.w += v4.w * w4;
        acc.x += v5.x * w5; acc.y += v5.y * w5; acc.z += v5.z * w5; acc.w += v5.w * w5;
        acc.x += v6.x * w6; acc.y += v6.y * w6; acc.z += v6.z * w6; acc.w += v6.w * w6;
        acc.x += v7.x * w7; acc.y += v7.y * w7; acc.z += v7.z * w7; acc.w += v7.w * w7;

        ob[t] = acc;
    }

    // A_full[m, j] = (j>>3 == m) ? tanh(blocks[j]) : 0 — written by the b==0 CTAs.
    // 1024 floats per row = 256 float4; one per thread.
    if (b == 0) {
        const int j0 = threadIdx.x * 4;   // column of first element in this float4
        float4 a;
        a.x = ((j0 + 0) >> 3 == m) ? ws[(j0 + 0) & 7] : 0.0f;
        a.y = ((j0 + 1) >> 3 == m) ? ws[(j0 + 1) & 7] : 0.0f;
        a.z = ((j0 + 2) >> 3 == m) ? ws[(j0 + 2) & 7] : 0.0f;
        a.w = ((j0 + 3) >> 3 == m) ? ws[(j0 + 3) & 7] : 0.0f;
        reinterpret_cast<float4*>(afull_out + (size_t)m * NCH)[threadIdx.x] = a;
    }
}

extern "C" void kernel_launch(void* const* d_in, const int* in_sizes, int n_in,
                              void* d_out, int out_size)
{
    const float* x      = (const float*)d_in[0];
    const float* blocks = (const float*)d_in[1];
    float* out = (float*)d_out;

    // Output layout: Ax (B*M*T floats) followed by A_full (M*NCH floats)
    float* ax_out    = out;
    float* afull_out = out + (size_t)BSZ * MOUT * TLEN;

    fused_kernel<<<BSZ * MOUT, 256>>>(x, blocks, ax_out, afull_out);
}